// round 2
// baseline (speedup 1.0000x reference)
#include <cuda_runtime.h>
#include <math.h>

// ---------------- shapes ----------------
#define BB     4
#define PP     2048
#define TOK    8192          // BB*PP
#define DM     1024          // d_model
#define NH     16
#define NKV    8
#define HDIM   64
#define FF     4096
#define NE     16
#define FEXP   256
#define BHT    64            // BB*NH

// ---------------- scratch (device globals; no allocation allowed) -------------
__device__ float g_h [ (size_t)TOK * DM ];          // rmsnorm1 out, later rmsnorm2 out
__device__ float g_q [ (size_t)TOK * NH * HDIM ];
__device__ float g_k [ (size_t)TOK * NKV * HDIM ];
__device__ float g_v [ (size_t)TOK * NKV * HDIM ];
__device__ float g_S [ (size_t)BHT * PP * PP ];     // attention scores/probs (1.07 GB)
__device__ float g_o [ (size_t)TOK * NH * HDIM ];
__device__ float g_b1[ (size_t)TOK * FF ];          // gate / act   (reused for expert act)
__device__ float g_b2[ (size_t)TOK * FF ];          // up           (reused for expert up)

// ---------------- generic tiled SGEMM core ----------------
// BM=128 fixed, BK=16, 256 threads, thread tile 8 x TN, BN/TN must be 16.
template<int BN, int TN, bool TRANSB>
__device__ __forceinline__ void gemm_core(
    const float* __restrict__ A, int lda,
    const float* __restrict__ B, int ldb,
    float* __restrict__ C, int ldc,
    const float* __restrict__ bias,
    const float* __restrict__ R, int ldr,
    int accumulate, int N, int K, float alpha, int m0, int n0)
{
    __shared__ float As[16][128 + 4];
    __shared__ float Bs[16][BN + 4];

    const int tid = threadIdx.x;
    const int tx  = tid & 15;   // col group
    const int ty  = tid >> 4;   // row group

    float acc[8][TN];
#pragma unroll
    for (int i = 0; i < 8; i++)
#pragma unroll
        for (int j = 0; j < TN; j++) acc[i][j] = 0.0f;

    for (int k0 = 0; k0 < K; k0 += 16) {
        // load A tile (128 x 16), coalesced along k
#pragma unroll
        for (int l = 0; l < 8; l++) {
            int idx = tid + l * 256;
            int r = idx >> 4, c = idx & 15;
            As[c][r] = A[(long long)(m0 + r) * lda + (k0 + c)];
        }
        // load B tile (16 x BN)
#pragma unroll
        for (int l = 0; l < BN / 16; l++) {
            int idx = tid + l * 256;
            if (TRANSB) {
                int nn = idx >> 4, c = idx & 15;
                Bs[c][nn] = (n0 + nn < N) ? B[(long long)(n0 + nn) * ldb + (k0 + c)] : 0.0f;
            } else {
                int nn = idx % BN, c = idx / BN;
                Bs[c][nn] = (n0 + nn < N) ? B[(long long)(k0 + c) * ldb + (n0 + nn)] : 0.0f;
            }
        }
        __syncthreads();

#pragma unroll
        for (int kk = 0; kk < 16; kk++) {
            float af[8], bf[TN];
#pragma unroll
            for (int i = 0; i < 8; i++)  af[i] = As[kk][ty * 8 + i];
#pragma unroll
            for (int j = 0; j < TN; j++) bf[j] = Bs[kk][tx * TN + j];
#pragma unroll
            for (int i = 0; i < 8; i++)
#pragma unroll
                for (int j = 0; j < TN; j++)
                    acc[i][j] += af[i] * bf[j];
        }
        __syncthreads();
    }

    // epilogue
#pragma unroll
    for (int i = 0; i < 8; i++) {
        int r = m0 + ty * 8 + i;
#pragma unroll
        for (int j = 0; j < TN; j++) {
            int col = n0 + tx * TN + j;
            if (col < N) {
                float vv = acc[i][j] * alpha;
                if (bias) vv += bias[col];
                if (R)    vv += R[(long long)r * ldr + col];
                long long ci = (long long)r * ldc + col;
                if (accumulate) C[ci] += vv; else C[ci] = vv;
            }
        }
    }
}

struct GemmArgs {
    const float* A; const float* B; float* C; const float* bias; const float* R;
    long long sAz, sBz, sCz, sRz;
    int lda, ldb, ldc, ldr;
    int N, K;
    float alpha;
    int accumulate;
};

__global__ void __launch_bounds__(256, 2) gemm_nn_k(GemmArgs a) {
    int z = blockIdx.z;
    const float* A = a.A + (long long)z * a.sAz;
    const float* B = a.B + (long long)z * a.sBz;
    float*       C = a.C + (long long)z * a.sCz;
    const float* R = a.R ? a.R + (long long)z * a.sRz : (const float*)0;
    gemm_core<128, 8, false>(A, a.lda, B, a.ldb, C, a.ldc, a.bias, R, a.ldr,
                             a.accumulate, a.N, a.K, a.alpha,
                             blockIdx.y * 128, blockIdx.x * 128);
}

// ---------------- attention-specific GEMMs ----------------
// S[bh] = (1/8) * Q[b,:,h,:] @ K[b,:,h/2,:]^T  with causal block skip
__global__ void __launch_bounds__(256, 2) attn_s_k(const float* __restrict__ q,
                                                   const float* __restrict__ k,
                                                   float* __restrict__ S)
{
    int z = blockIdx.z;
    int b = z / NH, h = z % NH;
    int m0 = blockIdx.y * 128, n0 = blockIdx.x * 128;
    if (n0 > m0 + 127) return;   // fully above diagonal -> masked anyway
    const float* A = q + (long long)b * PP * (NH * HDIM) + h * HDIM;
    const float* B = k + (long long)b * PP * (NKV * HDIM) + (h >> 1) * HDIM;
    float*       C = S + (long long)z * PP * PP;
    gemm_core<128, 8, true>(A, NH * HDIM, B, NKV * HDIM, C, PP,
                            (const float*)0, (const float*)0, 0,
                            0, PP, HDIM, 0.125f, m0, n0);
}

// O[b,:,h,:] = P[bh] @ V[b,:,h/2,:]  (K clipped to causal bound; masked probs are 0)
__global__ void __launch_bounds__(256, 2) attn_pv_k(const float* __restrict__ S,
                                                    const float* __restrict__ v,
                                                    float* __restrict__ o)
{
    int z = blockIdx.z;
    int b = z / NH, h = z % NH;
    int m0 = blockIdx.y * 128;
    const float* A = S + (long long)z * PP * PP;
    const float* B = v + (long long)b * PP * (NKV * HDIM) + (h >> 1) * HDIM;
    float*       C = o + (long long)b * PP * (NH * HDIM) + h * HDIM;
    int Keff = m0 + 128;                 // causal: pk <= p < m0+128
    gemm_core<64, 4, false>(A, PP, B, NKV * HDIM, C, NH * HDIM,
                            (const float*)0, (const float*)0, 0,
                            0, HDIM, Keff, 1.0f, m0, 0);
}

// ---------------- elementwise kernels ----------------
__global__ void rmsnorm_k(const float* __restrict__ x, const float* __restrict__ w,
                          float* __restrict__ y)
{
    long long base = (long long)blockIdx.x * DM;
    int tid = threadIdx.x;
    float vv[4];
    float ss = 0.0f;
#pragma unroll
    for (int l = 0; l < 4; l++) {
        vv[l] = x[base + tid + l * 256];
        ss += vv[l] * vv[l];
    }
    __shared__ float sm[256];
    sm[tid] = ss; __syncthreads();
    for (int s = 128; s > 0; s >>= 1) {
        if (tid < s) sm[tid] += sm[tid + s];
        __syncthreads();
    }
    float scale = rsqrtf(sm[0] / (float)DM + 1e-6f);
#pragma unroll
    for (int l = 0; l < 4; l++) {
        int c = tid + l * 256;
        y[base + c] = vv[l] * scale * w[c];
    }
}

__global__ void rope_k(float* __restrict__ buf, int nheads)
{
    int idx = blockIdx.x * blockDim.x + threadIdx.x;
    int total = TOK * nheads * (HDIM / 2);
    if (idx >= total) return;
    int i   = idx & 31;            // pair index 0..31
    int rem = idx >> 5;
    int hh  = rem % nheads;
    int t   = rem / nheads;
    int p   = t & (PP - 1);        // position within sequence
    float inv = expf(-(float)i * (1.0f / 32.0f) * 9.210340371976184f); // 10000^(-i/32)
    float ang = (float)p * inv;
    float c = cosf(ang), s = sinf(ang);
    float* base = buf + ((long long)t * nheads + hh) * HDIM;
    float v1 = base[i], v2 = base[i + 32];
    base[i]      = v1 * c - v2 * s;
    base[i + 32] = v2 * c + v1 * s;
}

__global__ void softmax_causal_k(float* __restrict__ S)
{
    int p  = blockIdx.x;
    int bh = blockIdx.y;
    float* row = S + ((long long)bh * PP + p) * PP;
    int tid = threadIdx.x;
    float vals[8];
    float mx = -3.0e38f;
#pragma unroll
    for (int l = 0; l < 8; l++) {
        int c = tid + l * 256;
        float v = row[c];
        if (c > p) v = -1.0e9f;
        vals[l] = v;
        mx = fmaxf(mx, v);
    }
    __shared__ float sm[256];
    sm[tid] = mx; __syncthreads();
    for (int s = 128; s > 0; s >>= 1) {
        if (tid < s) sm[tid] = fmaxf(sm[tid], sm[tid + s]);
        __syncthreads();
    }
    mx = sm[0]; __syncthreads();
    float sum = 0.0f;
#pragma unroll
    for (int l = 0; l < 8; l++) {
        vals[l] = expf(vals[l] - mx);
        sum += vals[l];
    }
    sm[tid] = sum; __syncthreads();
    for (int s = 128; s > 0; s >>= 1) {
        if (tid < s) sm[tid] += sm[tid + s];
        __syncthreads();
    }
    float inv = 1.0f / sm[0];
#pragma unroll
    for (int l = 0; l < 8; l++)
        row[tid + l * 256] = vals[l] * inv;
}

__global__ void silu_mul_k(const float* __restrict__ g, const float* __restrict__ u,
                           float* __restrict__ out, long long n)
{
    long long i = (long long)blockIdx.x * blockDim.x + threadIdx.x;
    if (i >= n) return;
    float x = g[i];
    float s = x / (1.0f + expf(-x));
    out[i] = s * u[i];
}

// expert act with routing-mask fold: out[t, e*256+f] = silu(g)*u*mask[t,e]
__global__ void expert_act_k(const float* __restrict__ g, const float* __restrict__ u,
                             const float* __restrict__ mask, float* __restrict__ out)
{
    long long i = (long long)blockIdx.x * blockDim.x + threadIdx.x;
    if (i >= (long long)TOK * (NE * FEXP)) return;
    int col = (int)(i & (NE * FEXP - 1));
    long long t = i >> 12;               // / 4096
    int e = col >> 8;                    // / FEXP
    float x = g[i];
    float s = x / (1.0f + expf(-x));
    out[i] = s * u[i] * mask[t * NE + e];
}

// ---------------- host side ----------------
static void launch_gemm(const float* A, long long sAz, int lda,
                        const float* B, long long sBz, int ldb,
                        float* C, long long sCz, int ldc,
                        const float* bias, const float* R, long long sRz, int ldr,
                        int M, int N, int K, float alpha, int acc, int batch)
{
    GemmArgs a;
    a.A = A; a.B = B; a.C = C; a.bias = bias; a.R = R;
    a.sAz = sAz; a.sBz = sBz; a.sCz = sCz; a.sRz = sRz;
    a.lda = lda; a.ldb = ldb; a.ldc = ldc; a.ldr = ldr;
    a.N = N; a.K = K; a.alpha = alpha; a.accumulate = acc;
    dim3 grid((N + 127) / 128, M / 128, batch);
    gemm_nn_k<<<grid, 256>>>(a);
}

extern "C" void kernel_launch(void* const* d_in, const int* in_sizes, int n_in,
                              void* d_out, int out_size)
{
    const float* x           = (const float*)d_in[0];
    const float* expert_mask = (const float*)d_in[1];
    const float* ln1_w       = (const float*)d_in[2];
    const float* wq          = (const float*)d_in[3];
    const float* bq          = (const float*)d_in[4];
    const float* wk          = (const float*)d_in[5];
    const float* bk          = (const float*)d_in[6];
    const float* wv          = (const float*)d_in[7];
    const float* bv          = (const float*)d_in[8];
    const float* wo          = (const float*)d_in[9];
    const float* ln2_w       = (const float*)d_in[10];
    const float* w_gate      = (const float*)d_in[11];
    const float* w_up        = (const float*)d_in[12];
    const float* w_down      = (const float*)d_in[13];
    const float* we_gate     = (const float*)d_in[14];
    const float* we_up       = (const float*)d_in[15];
    const float* we_down     = (const float*)d_in[16];
    float* out = (float*)d_out;

    float *h, *q, *k, *v, *S, *o, *b1, *b2;
    cudaGetSymbolAddress((void**)&h,  g_h);
    cudaGetSymbolAddress((void**)&q,  g_q);
    cudaGetSymbolAddress((void**)&k,  g_k);
    cudaGetSymbolAddress((void**)&v,  g_v);
    cudaGetSymbolAddress((void**)&S,  g_S);
    cudaGetSymbolAddress((void**)&o,  g_o);
    cudaGetSymbolAddress((void**)&b1, g_b1);
    cudaGetSymbolAddress((void**)&b2, g_b2);

    // 1. h = rmsnorm(x, ln1_w)
    rmsnorm_k<<<TOK, 256>>>(x, ln1_w, h);

    // 2. q/k/v projections (+bias)
    launch_gemm(h, 0, DM, wq, 0, NH * HDIM,  q, 0, NH * HDIM,  bq, 0, 0, 0,
                TOK, NH * HDIM,  DM, 1.0f, 0, 1);
    launch_gemm(h, 0, DM, wk, 0, NKV * HDIM, k, 0, NKV * HDIM, bk, 0, 0, 0,
                TOK, NKV * HDIM, DM, 1.0f, 0, 1);
    launch_gemm(h, 0, DM, wv, 0, NKV * HDIM, v, 0, NKV * HDIM, bv, 0, 0, 0,
                TOK, NKV * HDIM, DM, 1.0f, 0, 1);

    // 3. RoPE on q and k
    rope_k<<<(TOK * NH  * 32 + 255) / 256, 256>>>(q, NH);
    rope_k<<<(TOK * NKV * 32 + 255) / 256, 256>>>(k, NKV);

    // 4. S = QK^T / 8  (causal block skip)
    {
        dim3 grid(PP / 128, PP / 128, BHT);
        attn_s_k<<<grid, 256>>>(q, k, S);
    }

    // 5. causal softmax in-place
    {
        dim3 grid(PP, BHT);
        softmax_causal_k<<<grid, 256>>>(S);
    }

    // 6. O = P @ V
    {
        dim3 grid(1, PP / 128, BHT);
        attn_pv_k<<<grid, 256>>>(S, v, o);
    }

    // 7. out = x + O @ wo   (writes every element of d_out)
    launch_gemm(o, 0, NH * HDIM, wo, 0, DM, out, 0, DM,
                (const float*)0, x, 0, DM,
                TOK, DM, NH * HDIM, 1.0f, 0, 1);

    // 8. h2 = rmsnorm(out, ln2_w)  (reuse h buffer)
    rmsnorm_k<<<TOK, 256>>>(out, ln2_w, h);

    // 9. dense MLP: b1 = h@w_gate, b2 = h@w_up, b1 = silu(b1)*b2, out += b1@w_down
    launch_gemm(h, 0, DM, w_gate, 0, FF, b1, 0, FF, (const float*)0,
                (const float*)0, 0, 0, TOK, FF, DM, 1.0f, 0, 1);
    launch_gemm(h, 0, DM, w_up,   0, FF, b2, 0, FF, (const float*)0,
                (const float*)0, 0, 0, TOK, FF, DM, 1.0f, 0, 1);
    {
        long long n = (long long)TOK * FF;
        silu_mul_k<<<(unsigned)((n + 255) / 256), 256>>>(b1, b2, b1, n);
    }
    launch_gemm(b1, 0, FF, w_down, 0, DM, out, 0, DM, (const float*)0,
                (const float*)0, 0, 0, TOK, DM, FF, 1.0f, 1, 1);

    // 10. experts: b1[t, e*256+f] = h @ we_gate[e], b2 likewise (batched over e)
    launch_gemm(h, 0, DM, we_gate, (long long)DM * FEXP, FEXP,
                b1, FEXP, NE * FEXP, (const float*)0, (const float*)0, 0, 0,
                TOK, FEXP, DM, 1.0f, 0, NE);
    launch_gemm(h, 0, DM, we_up,   (long long)DM * FEXP, FEXP,
                b2, FEXP, NE * FEXP, (const float*)0, (const float*)0, 0, 0,
                TOK, FEXP, DM, 1.0f, 0, NE);

    // 11. b1 = silu(b1)*b2*mask  then  out += b1 @ we_down_flat[4096,1024]
    {
        long long n = (long long)TOK * NE * FEXP;
        expert_act_k<<<(unsigned)((n + 255) / 256), 256>>>(b1, b2, expert_mask, b1);
    }
    launch_gemm(b1, 0, NE * FEXP, we_down, 0, DM, out, 0, DM, (const float*)0,
                (const float*)0, 0, 0, TOK, DM, NE * FEXP, 1.0f, 1, 1);
}

// round 4
// speedup vs baseline: 2.7276x; 2.7276x over previous
#include <cuda_runtime.h>
#include <math.h>
#include <stdint.h>

// ---------------- shapes ----------------
#define BB     4
#define PP     2048
#define TOK    8192          // BB*PP
#define DM     1024          // d_model
#define NH     16
#define NKV    8
#define HDIM   64
#define FF     4096
#define NE     16
#define FEXP   256
#define BHT    64            // BB*NH

// ---------------- scratch (device globals; no allocation allowed) -------------
__device__ float g_h [ (size_t)TOK * DM ];
__device__ float g_q [ (size_t)TOK * NH * HDIM ];
__device__ float g_k [ (size_t)TOK * NKV * HDIM ];
__device__ float g_v [ (size_t)TOK * NKV * HDIM ];
__device__ float g_S [ (size_t)BHT * PP * PP ];     // 1.07 GB
__device__ float g_o [ (size_t)TOK * NH * HDIM ];
__device__ float g_b1[ (size_t)TOK * FF ];
__device__ float g_b2[ (size_t)TOK * FF ];

// ---------------- tf32 mma helpers ----------------
__device__ __forceinline__ uint32_t f2tf(float x) {
    uint32_t r;
    asm("cvt.rna.tf32.f32 %0, %1;" : "=r"(r) : "f"(x));
    return r;
}

__device__ __forceinline__ void mma_tf32(float4& d, const uint32_t a[4], const uint32_t b[2]) {
    asm volatile(
        "mma.sync.aligned.m16n8k8.row.col.f32.tf32.tf32.f32 "
        "{%0,%1,%2,%3}, {%4,%5,%6,%7}, {%8,%9}, {%0,%1,%2,%3};\n"
        : "+f"(d.x), "+f"(d.y), "+f"(d.z), "+f"(d.w)
        : "r"(a[0]), "r"(a[1]), "r"(a[2]), "r"(a[3]), "r"(b[0]), "r"(b[1]));
}

__device__ __forceinline__ void cp16(uint32_t dst, const void* src) {
    asm volatile("cp.async.ca.shared.global [%0], [%1], 16;\n" :: "r"(dst), "l"(src));
}
__device__ __forceinline__ void cp16z(uint32_t dst, const void* src, int srcsize) {
    asm volatile("cp.async.ca.shared.global [%0], [%1], 16, %2;\n"
                 :: "r"(dst), "l"(src), "r"(srcsize));
}
__device__ __forceinline__ void cp_commit() { asm volatile("cp.async.commit_group;\n"); }
__device__ __forceinline__ void cp_wait0()  { asm volatile("cp.async.wait_group 0;\n"); }
__device__ __forceinline__ void cp_wait1()  { asm volatile("cp.async.wait_group 1;\n"); }

// ---------------- tf32 GEMM core ----------------
// BM=128, BN=128, BK=32, 256 threads (8 warps in 4x2), warp tile 32x64.
// A row-major [M,K] (k contiguous).  TRANSB=false: B row-major [K,N].
// TRANSB=true: B row-major [N,K] (i.e. C = A @ B^T).
// smem (dynamic):
//   As: [2][128][36] floats
//   Bs: TRANSB ? [2][128][36] : [2][32][132]
#define AS_ELEMS (2*128*36)
#define BS_NN_ELEMS (2*32*132)
#define BS_TB_ELEMS (2*128*36)
#define SMEM_NN_BYTES ((AS_ELEMS + BS_NN_ELEMS)*4)
#define SMEM_TB_BYTES ((AS_ELEMS + BS_TB_ELEMS)*4)

template<bool TRANSB>
__device__ __forceinline__ void tf32_core(
    const float* __restrict__ A, int lda,
    const float* __restrict__ B, int ldb,
    float* __restrict__ C, int ldc,
    const float* __restrict__ bias,
    const float* __restrict__ R, int ldr,
    int accumulate, int N, int K, float alpha, int m0, int n0)
{
    extern __shared__ float smf[];
    float* As  = smf;
    float* Bsm = smf + AS_ELEMS;

    const int tid  = threadIdx.x;
    const int lane = tid & 31;
    const int warp = tid >> 5;
    const int wm   = (warp >> 1) * 32;   // warp row offset in tile
    const int wn   = (warp & 1) * 64;    // warp col offset in tile
    const int g    = lane >> 2;          // group id 0..7
    const int t    = lane & 3;           // thread-in-group 0..3

    uint32_t As_u = (uint32_t)__cvta_generic_to_shared(As);
    uint32_t Bs_u = (uint32_t)__cvta_generic_to_shared(Bsm);

    float4 acc[2][8];
#pragma unroll
    for (int i = 0; i < 2; i++)
#pragma unroll
        for (int j = 0; j < 8; j++) acc[i][j] = make_float4(0.f, 0.f, 0.f, 0.f);

    const int niter = K >> 5;   // K/32

    auto issue = [&](int it) {
        int buf = it & 1;
        int k0  = it << 5;
        // A tile: 128 rows x 32 k, float4 along k
#pragma unroll
        for (int l = 0; l < 4; l++) {
            int chunk = tid + l * 256;
            int row = chunk >> 3;
            int kk  = (chunk & 7) << 2;
            cp16(As_u + (((buf << 7) + row) * 36 + kk) * 4,
                 A + (long long)(m0 + row) * lda + k0 + kk);
        }
        if (TRANSB) {
            // B[n][k] -> Bs[n][k], float4 along k
#pragma unroll
            for (int l = 0; l < 4; l++) {
                int chunk = tid + l * 256;
                int row = chunk >> 3;
                int kk  = (chunk & 7) << 2;
                cp16(Bs_u + (((buf << 7) + row) * 36 + kk) * 4,
                     B + (long long)(n0 + row) * ldb + k0 + kk);
            }
        } else {
            // B[k][n] -> Bs[k][n], float4 along n, zero-fill n >= N
#pragma unroll
            for (int l = 0; l < 4; l++) {
                int chunk = tid + l * 256;
                int kk = chunk >> 5;
                int nn = (chunk & 31) << 2;
                int sz = (n0 + nn < N) ? 16 : 0;
                cp16z(Bs_u + ((buf * 32 + kk) * 132 + nn) * 4,
                      B + (long long)(k0 + kk) * ldb + n0 + nn, sz);
            }
        }
        cp_commit();
    };

    issue(0);
    for (int it = 0; it < niter; ++it) {
        if (it + 1 < niter) { issue(it + 1); cp_wait1(); }
        else                { cp_wait0(); }
        __syncthreads();

        const float* Ab = As  + (it & 1) * (128 * 36);
        const float* Bb = TRANSB ? (Bsm + (it & 1) * (128 * 36))
                                 : (Bsm + (it & 1) * (32 * 132));
#pragma unroll
        for (int ks = 0; ks < 4; ks++) {
            int k = ks * 8;
            uint32_t af[2][4];
#pragma unroll
            for (int tm = 0; tm < 2; tm++) {
                int r = wm + tm * 16;
                af[tm][0] = f2tf(Ab[(r + g)     * 36 + k + t]);
                af[tm][1] = f2tf(Ab[(r + 8 + g) * 36 + k + t]);
                af[tm][2] = f2tf(Ab[(r + g)     * 36 + k + 4 + t]);
                af[tm][3] = f2tf(Ab[(r + 8 + g) * 36 + k + 4 + t]);
            }
            uint32_t bf[8][2];
#pragma unroll
            for (int tn = 0; tn < 8; tn++) {
                int c = wn + tn * 8;
                if (TRANSB) {
                    bf[tn][0] = f2tf(Bb[(c + g) * 36 + k + t]);
                    bf[tn][1] = f2tf(Bb[(c + g) * 36 + k + 4 + t]);
                } else {
                    bf[tn][0] = f2tf(Bb[(k + t)     * 132 + c + g]);
                    bf[tn][1] = f2tf(Bb[(k + 4 + t) * 132 + c + g]);
                }
            }
#pragma unroll
            for (int tm = 0; tm < 2; tm++)
#pragma unroll
                for (int tn = 0; tn < 8; tn++)
                    mma_tf32(acc[tm][tn], af[tm], bf[tn]);
        }
        __syncthreads();
    }

    // epilogue
#pragma unroll
    for (int tm = 0; tm < 2; tm++) {
        int r0 = m0 + wm + tm * 16 + g;
#pragma unroll
        for (int tn = 0; tn < 8; tn++) {
            int c0 = n0 + wn + tn * 8 + t * 2;
            float4 d = acc[tm][tn];
            float vals[4] = { d.x, d.y, d.z, d.w };
            int   rows[4] = { r0, r0, r0 + 8, r0 + 8 };
            int   cols[4] = { c0, c0 + 1, c0, c0 + 1 };
#pragma unroll
            for (int e = 0; e < 4; e++) {
                int col = cols[e];
                if (col < N) {
                    float vv = vals[e] * alpha;
                    if (bias) vv += bias[col];
                    if (R)    vv += R[(long long)rows[e] * ldr + col];
                    long long ci = (long long)rows[e] * ldc + col;
                    if (accumulate) C[ci] += vv; else C[ci] = vv;
                }
            }
        }
    }
}

struct GemmArgs {
    const float* A; const float* B; float* C; const float* bias; const float* R;
    long long sAz, sBz, sCz, sRz;
    int lda, ldb, ldc, ldr;
    int N, K;
    float alpha;
    int accumulate;
};

__global__ void __launch_bounds__(256, 2) tf32_gemm_nn_k(GemmArgs a) {
    int z = blockIdx.z;
    const float* A = a.A + (long long)z * a.sAz;
    const float* B = a.B + (long long)z * a.sBz;
    float*       C = a.C + (long long)z * a.sCz;
    const float* R = a.R ? a.R + (long long)z * a.sRz : (const float*)0;
    tf32_core<false>(A, a.lda, B, a.ldb, C, a.ldc, a.bias, R, a.ldr,
                     a.accumulate, a.N, a.K, a.alpha,
                     blockIdx.y * 128, blockIdx.x * 128);
}

// S[bh] = (1/8) * Q[b,:,h,:] @ K[b,:,h/2,:]^T  with causal block skip
__global__ void __launch_bounds__(256, 2) attn_s_k(const float* __restrict__ q,
                                                   const float* __restrict__ k,
                                                   float* __restrict__ S)
{
    int z = blockIdx.z;
    int b = z / NH, h = z % NH;
    int m0 = blockIdx.y * 128, n0 = blockIdx.x * 128;
    if (n0 > m0 + 127) return;
    const float* A = q + (long long)b * PP * (NH * HDIM) + h * HDIM;
    const float* B = k + (long long)b * PP * (NKV * HDIM) + (h >> 1) * HDIM;
    float*       C = S + (long long)z * PP * PP;
    tf32_core<true>(A, NH * HDIM, B, NKV * HDIM, C, PP,
                    (const float*)0, (const float*)0, 0,
                    0, PP, HDIM, 0.125f, m0, n0);
}

// O[b,:,h,:] = P[bh] @ V[b,:,h/2,:]  (K clipped to causal bound; masked probs are 0)
__global__ void __launch_bounds__(256, 2) attn_pv_k(const float* __restrict__ S,
                                                    const float* __restrict__ v,
                                                    float* __restrict__ o)
{
    int z = blockIdx.z;
    int b = z / NH, h = z % NH;
    int m0 = blockIdx.y * 128;
    const float* A = S + (long long)z * PP * PP;
    const float* B = v + (long long)b * PP * (NKV * HDIM) + (h >> 1) * HDIM;
    float*       C = o + (long long)b * PP * (NH * HDIM) + h * HDIM;
    int Keff = m0 + 128;
    tf32_core<false>(A, PP, B, NKV * HDIM, C, NH * HDIM,
                     (const float*)0, (const float*)0, 0,
                     0, HDIM, Keff, 1.0f, m0, 0);
}

// ---------------- elementwise kernels ----------------
__global__ void rmsnorm_k(const float* __restrict__ x, const float* __restrict__ w,
                          float* __restrict__ y)
{
    long long base = (long long)blockIdx.x * DM;
    int tid = threadIdx.x;
    float vv[4];
    float ss = 0.0f;
#pragma unroll
    for (int l = 0; l < 4; l++) {
        vv[l] = x[base + tid + l * 256];
        ss += vv[l] * vv[l];
    }
    __shared__ float sm[256];
    sm[tid] = ss; __syncthreads();
    for (int s = 128; s > 0; s >>= 1) {
        if (tid < s) sm[tid] += sm[tid + s];
        __syncthreads();
    }
    float scale = rsqrtf(sm[0] / (float)DM + 1e-6f);
#pragma unroll
    for (int l = 0; l < 4; l++) {
        int c = tid + l * 256;
        y[base + c] = vv[l] * scale * w[c];
    }
}

__global__ void rope_k(float* __restrict__ buf, int nheads)
{
    int idx = blockIdx.x * blockDim.x + threadIdx.x;
    int total = TOK * nheads * (HDIM / 2);
    if (idx >= total) return;
    int i   = idx & 31;
    int rem = idx >> 5;
    int hh  = rem % nheads;
    int t   = rem / nheads;
    int p   = t & (PP - 1);
    float inv = expf(-(float)i * (1.0f / 32.0f) * 9.210340371976184f);
    float ang = (float)p * inv;
    float c = cosf(ang), s = sinf(ang);
    float* base = buf + ((long long)t * nheads + hh) * HDIM;
    float v1 = base[i], v2 = base[i + 32];
    base[i]      = v1 * c - v2 * s;
    base[i + 32] = v2 * c + v1 * s;
}

__global__ void softmax_causal_k(float* __restrict__ S)
{
    int p  = blockIdx.x;
    int bh = blockIdx.y;
    float* row = S + ((long long)bh * PP + p) * PP;
    int tid = threadIdx.x;
    float vals[8];
    float mx = -3.0e38f;
#pragma unroll
    for (int l = 0; l < 8; l++) {
        int c = tid + l * 256;
        float v = row[c];
        if (c > p) v = -1.0e9f;
        vals[l] = v;
        mx = fmaxf(mx, v);
    }
    __shared__ float sm[256];
    sm[tid] = mx; __syncthreads();
    for (int s = 128; s > 0; s >>= 1) {
        if (tid < s) sm[tid] = fmaxf(sm[tid], sm[tid + s]);
        __syncthreads();
    }
    mx = sm[0]; __syncthreads();
    float sum = 0.0f;
#pragma unroll
    for (int l = 0; l < 8; l++) {
        vals[l] = expf(vals[l] - mx);
        sum += vals[l];
    }
    sm[tid] = sum; __syncthreads();
    for (int s = 128; s > 0; s >>= 1) {
        if (tid < s) sm[tid] += sm[tid + s];
        __syncthreads();
    }
    float inv = 1.0f / sm[0];
#pragma unroll
    for (int l = 0; l < 8; l++)
        row[tid + l * 256] = vals[l] * inv;
}

__global__ void silu_mul_k(const float* __restrict__ g, const float* __restrict__ u,
                           float* __restrict__ out, long long n)
{
    long long i = (long long)blockIdx.x * blockDim.x + threadIdx.x;
    if (i >= n) return;
    float x = g[i];
    float s = x / (1.0f + expf(-x));
    out[i] = s * u[i];
}

__global__ void expert_act_k(const float* __restrict__ g, const float* __restrict__ u,
                             const float* __restrict__ mask, float* __restrict__ out)
{
    long long i = (long long)blockIdx.x * blockDim.x + threadIdx.x;
    if (i >= (long long)TOK * (NE * FEXP)) return;
    long long t = i >> 12;
    int col = (int)(i & (NE * FEXP - 1));
    int e = col >> 8;
    float x = g[i];
    float s = x / (1.0f + expf(-x));
    out[i] = s * u[i] * mask[t * NE + e];
}

// ---------------- host side ----------------
static void launch_gemm(const float* A, long long sAz, int lda,
                        const float* B, long long sBz, int ldb,
                        float* C, long long sCz, int ldc,
                        const float* bias, const float* R, long long sRz, int ldr,
                        int M, int N, int K, float alpha, int acc, int batch)
{
    GemmArgs a;
    a.A = A; a.B = B; a.C = C; a.bias = bias; a.R = R;
    a.sAz = sAz; a.sBz = sBz; a.sCz = sCz; a.sRz = sRz;
    a.lda = lda; a.ldb = ldb; a.ldc = ldc; a.ldr = ldr;
    a.N = N; a.K = K; a.alpha = alpha; a.accumulate = acc;
    dim3 grid((N + 127) / 128, M / 128, batch);
    tf32_gemm_nn_k<<<grid, 256, SMEM_NN_BYTES>>>(a);
}

extern "C" void kernel_launch(void* const* d_in, const int* in_sizes, int n_in,
                              void* d_out, int out_size)
{
    const float* x           = (const float*)d_in[0];
    const float* expert_mask = (const float*)d_in[1];
    const float* ln1_w       = (const float*)d_in[2];
    const float* wq          = (const float*)d_in[3];
    const float* bq          = (const float*)d_in[4];
    const float* wk          = (const float*)d_in[5];
    const float* bk          = (const float*)d_in[6];
    const float* wv          = (const float*)d_in[7];
    const float* bv          = (const float*)d_in[8];
    const float* wo          = (const float*)d_in[9];
    const float* ln2_w       = (const float*)d_in[10];
    const float* w_gate      = (const float*)d_in[11];
    const float* w_up        = (const float*)d_in[12];
    const float* w_down      = (const float*)d_in[13];
    const float* we_gate     = (const float*)d_in[14];
    const float* we_up       = (const float*)d_in[15];
    const float* we_down     = (const float*)d_in[16];
    float* out = (float*)d_out;

    cudaFuncSetAttribute(tf32_gemm_nn_k, cudaFuncAttributeMaxDynamicSharedMemorySize, SMEM_NN_BYTES);
    cudaFuncSetAttribute(attn_s_k,       cudaFuncAttributeMaxDynamicSharedMemorySize, SMEM_TB_BYTES);
    cudaFuncSetAttribute(attn_pv_k,      cudaFuncAttributeMaxDynamicSharedMemorySize, SMEM_NN_BYTES);

    float *h, *q, *k, *v, *S, *o, *b1, *b2;
    cudaGetSymbolAddress((void**)&h,  g_h);
    cudaGetSymbolAddress((void**)&q,  g_q);
    cudaGetSymbolAddress((void**)&k,  g_k);
    cudaGetSymbolAddress((void**)&v,  g_v);
    cudaGetSymbolAddress((void**)&S,  g_S);
    cudaGetSymbolAddress((void**)&o,  g_o);
    cudaGetSymbolAddress((void**)&b1, g_b1);
    cudaGetSymbolAddress((void**)&b2, g_b2);

    // 1. h = rmsnorm(x, ln1_w)
    rmsnorm_k<<<TOK, 256>>>(x, ln1_w, h);

    // 2. q/k/v projections (+bias)
    launch_gemm(h, 0, DM, wq, 0, NH * HDIM,  q, 0, NH * HDIM,  bq, 0, 0, 0,
                TOK, NH * HDIM,  DM, 1.0f, 0, 1);
    launch_gemm(h, 0, DM, wk, 0, NKV * HDIM, k, 0, NKV * HDIM, bk, 0, 0, 0,
                TOK, NKV * HDIM, DM, 1.0f, 0, 1);
    launch_gemm(h, 0, DM, wv, 0, NKV * HDIM, v, 0, NKV * HDIM, bv, 0, 0, 0,
                TOK, NKV * HDIM, DM, 1.0f, 0, 1);

    // 3. RoPE on q and k
    rope_k<<<(TOK * NH  * 32 + 255) / 256, 256>>>(q, NH);
    rope_k<<<(TOK * NKV * 32 + 255) / 256, 256>>>(k, NKV);

    // 4. S = QK^T / 8  (causal block skip)
    {
        dim3 grid(PP / 128, PP / 128, BHT);
        attn_s_k<<<grid, 256, SMEM_TB_BYTES>>>(q, k, S);
    }

    // 5. causal softmax in-place
    {
        dim3 grid(PP, BHT);
        softmax_causal_k<<<grid, 256>>>(S);
    }

    // 6. O = P @ V
    {
        dim3 grid(1, PP / 128, BHT);
        attn_pv_k<<<grid, 256, SMEM_NN_BYTES>>>(S, v, o);
    }

    // 7. out = x + O @ wo
    launch_gemm(o, 0, NH * HDIM, wo, 0, DM, out, 0, DM,
                (const float*)0, x, 0, DM,
                TOK, DM, NH * HDIM, 1.0f, 0, 1);

    // 8. h2 = rmsnorm(out, ln2_w)
    rmsnorm_k<<<TOK, 256>>>(out, ln2_w, h);

    // 9. dense MLP
    launch_gemm(h, 0, DM, w_gate, 0, FF, b1, 0, FF, (const float*)0,
                (const float*)0, 0, 0, TOK, FF, DM, 1.0f, 0, 1);
    launch_gemm(h, 0, DM, w_up,   0, FF, b2, 0, FF, (const float*)0,
                (const float*)0, 0, 0, TOK, FF, DM, 1.0f, 0, 1);
    {
        long long n = (long long)TOK * FF;
        silu_mul_k<<<(unsigned)((n + 255) / 256), 256>>>(b1, b2, b1, n);
    }
    launch_gemm(b1, 0, FF, w_down, 0, DM, out, 0, DM, (const float*)0,
                (const float*)0, 0, 0, TOK, DM, FF, 1.0f, 1, 1);

    // 10. experts (batched over e)
    launch_gemm(h, 0, DM, we_gate, (long long)DM * FEXP, FEXP,
                b1, FEXP, NE * FEXP, (const float*)0, (const float*)0, 0, 0,
                TOK, FEXP, DM, 1.0f, 0, NE);
    launch_gemm(h, 0, DM, we_up,   (long long)DM * FEXP, FEXP,
                b2, FEXP, NE * FEXP, (const float*)0, (const float*)0, 0, 0,
                TOK, FEXP, DM, 1.0f, 0, NE);

    // 11. routed combine + down
    {
        long long n = (long long)TOK * NE * FEXP;
        expert_act_k<<<(unsigned)((n + 255) / 256), 256>>>(b1, b2, expert_mask, b1);
    }
    launch_gemm(b1, 0, NE * FEXP, we_down, 0, DM, out, 0, DM, (const float*)0,
                (const float*)0, 0, 0, TOK, DM, NE * FEXP, 1.0f, 1, 1);
}